// round 17
// baseline (speedup 1.0000x reference)
#include <cuda_runtime.h>
#include <cuda_bf16.h>
#include <stdint.h>
#include <math.h>

#define HW 65536
#define WIMG 256
#define CH 128
#define BB 4
#define ELT (BB*CH*HW)

// ---------------- scratch ----------------
__device__ float g_V[ELT];
__device__ float g_Qb[ELT];
__device__ float g_Kb[ELT];
__device__ float g_OUT[ELT];
__device__ float g_T1[ELT];
__device__ float g_T2[ELT];
__device__ float g_F[BB*32*HW];
__device__ float g_OFF[BB*2*HW];
__device__ float g_FMC[BB*HW];
__device__ float g_SA[BB*HW];
__device__ float g_FSUM[BB*32];
__device__ float g_CA[BB*CH];
__device__ float g_MASK[BB*256];
__device__ __align__(16) __nv_bfloat16 g_WT[5][2][128*136];
__device__ __align__(16) __nv_bfloat16 g_WRIN[2][32*136];

__device__ __forceinline__ float leakyf(float x) { return x > 0.f ? x : 0.2f * x; }

__global__ void zero_fsum_kernel() {
    g_FSUM[threadIdx.x] = 0.f;
}

// ---------------- weight prep ----------------
__global__ void prep_all_kernel(const float* __restrict__ w0, const float* __restrict__ w1,
                                const float* __restrict__ w2, const float* __restrict__ w3,
                                const float* __restrict__ w4) {
    int set = blockIdx.y;
    const float* w = (set == 0) ? w0 : (set == 1) ? w1 : (set == 2) ? w2 : (set == 3) ? w3 : w4;
    int i = blockIdx.x * 256 + threadIdx.x;
    int oc = i >> 7, ci = i & 127;
    float v = w[i];
    __nv_bfloat16 h = __float2bfloat16_rn(v);
    __nv_bfloat16 l = __float2bfloat16_rn(v - __bfloat162float(h));
    g_WT[set][0][oc * 136 + ci] = h;
    g_WT[set][1][oc * 136 + ci] = l;
}

__global__ void prep_rin_kernel(const float* __restrict__ w) {
    int i = blockIdx.x * 256 + threadIdx.x;   // 4096
    int oc = i >> 7, ci = i & 127;
    float v = w[oc * 131 + ci];
    __nv_bfloat16 h = __float2bfloat16_rn(v);
    __nv_bfloat16 l = __float2bfloat16_rn(v - __bfloat162float(h));
    g_WRIN[0][oc * 136 + ci] = h;
    g_WRIN[1][oc * 136 + ci] = l;
}

// ---------------- HMMA m16n8k16 bf16 + ldmatrix ----------------
#define MMA_BF16(d, a, b) \
    asm volatile("mma.sync.aligned.m16n8k16.row.col.f32.bf16.bf16.f32 " \
        "{%0,%1,%2,%3}, {%4,%5,%6,%7}, {%8,%9}, {%0,%1,%2,%3};" \
        : "+f"((d)[0]), "+f"((d)[1]), "+f"((d)[2]), "+f"((d)[3]) \
        : "r"((a)[0]), "r"((a)[1]), "r"((a)[2]), "r"((a)[3]), "r"((b)[0]), "r"((b)[1]))

#define LDSM_X4(r, a) \
    asm volatile("ldmatrix.sync.aligned.m8n8.x4.shared.b16 {%0,%1,%2,%3}, [%4];" \
        : "=r"((r)[0]), "=r"((r)[1]), "=r"((r)[2]), "=r"((r)[3]) : "r"(a))

__device__ __forceinline__ uint32_t smaddr(const void* p) {
    return (uint32_t)__cvta_generic_to_shared(p);
}

// ---- GEMM body (half-window, 8-warp slice): used by convqk ----
__device__ __forceinline__ void gemm_body_128(
    const __nv_bfloat16* Wh, const __nv_bfloat16* Wl,
    const __nv_bfloat16* Xh, const __nv_bfloat16* Xl,
    const float* __restrict__ bias, float* __restrict__ yb,
    int py0, int px0, int half, int w, int lane) {
    int oc0 = (w & 3) * 32;
    int n0 = (w >> 2) * 64;
    int gid = lane >> 2, tig = lane & 3;
    int mm = lane >> 3, r8 = lane & 7;
    uint32_t aoff = (uint32_t)((oc0 + (mm & 1) * 8 + r8) * 272 + (mm >> 1) * 16);
    uint32_t aHi = smaddr(Wh) + aoff;
    uint32_t aLo = smaddr(Wl) + aoff;
    uint32_t boff = (uint32_t)((n0 + (mm >> 1) * 8 + r8) * 272 + (mm & 1) * 16);
    uint32_t bHi = smaddr(Xh) + boff;
    uint32_t bLo = smaddr(Xl) + boff;

    float acc[16][4];
#pragma unroll
    for (int i = 0; i < 16; i++)
#pragma unroll
        for (int j = 0; j < 4; j++) acc[i][j] = 0.f;

#pragma unroll 1
    for (int ks = 0; ks < 8; ks++) {
        uint32_t ko = ks * 32;
        uint32_t Ah[2][4], Al[2][4], Bh[4][4], Bl[4][4];
        LDSM_X4(Ah[0], aHi + ko);
        LDSM_X4(Ah[1], aHi + 16 * 272 + ko);
        LDSM_X4(Al[0], aLo + ko);
        LDSM_X4(Al[1], aLo + 16 * 272 + ko);
#pragma unroll
        for (int p = 0; p < 4; p++) {
            LDSM_X4(Bh[p], bHi + p * (16 * 272) + ko);
            LDSM_X4(Bl[p], bLo + p * (16 * 272) + ko);
        }
#pragma unroll
        for (int mt = 0; mt < 2; mt++)
#pragma unroll
            for (int nt = 0; nt < 8; nt++) {
                const uint32_t* bh = &Bh[nt >> 1][(nt & 1) * 2];
                const uint32_t* bl = &Bl[nt >> 1][(nt & 1) * 2];
                MMA_BF16(acc[mt * 8 + nt], Ah[mt], bh);
                MMA_BF16(acc[mt * 8 + nt], Ah[mt], bl);
                MMA_BF16(acc[mt * 8 + nt], Al[mt], bh);
            }
    }
#pragma unroll
    for (int mt = 0; mt < 2; mt++) {
        int ocA = oc0 + mt * 16 + gid;
        int ocB = ocA + 8;
        float bvA = __ldg(&bias[ocA]);
        float bvB = __ldg(&bias[ocB]);
#pragma unroll
        for (int nt = 0; nt < 8; nt++) {
            int col = n0 + nt * 8 + tig * 2;
            int p = half * 128 + col;
            int pix = (py0 + (p >> 4)) * 256 + px0 + (p & 15);
            float2 v0 = make_float2(acc[mt * 8 + nt][0] + bvA, acc[mt * 8 + nt][1] + bvA);
            float2 v1 = make_float2(acc[mt * 8 + nt][2] + bvB, acc[mt * 8 + nt][3] + bvB);
            *(float2*)(yb + (size_t)ocA * HW + pix) = v0;
            *(float2*)(yb + (size_t)ocB * HW + pix) = v1;
        }
    }
}

// ---------------- conv1x1 GEMM, QUARTER window per block (256 thr, 32x32 warp tiles, 2 blk/SM) ----
// smem: Wh|Wl (128*136 each) + Xh|Xl (64*136 each) = 104448 B
#define CV_SMEM_Q ((2 * 128 * 136 + 2 * 64 * 136) * 2)
__global__ void __launch_bounds__(256, 2)
conv1x1_mma(const float* __restrict__ xin, const __nv_bfloat16* __restrict__ wsp,
            const float* __restrict__ bias, float* __restrict__ yout, int bOff) {
    int bx = blockIdx.x;
    int n = bx >> 2, q = bx & 3;
    int b = blockIdx.y + bOff;
    extern __shared__ __nv_bfloat16 smb[];
    __nv_bfloat16* Wh = smb;
    __nv_bfloat16* Wl = Wh + 128 * 136;
    __nv_bfloat16* Xh = Wl + 128 * 136;
    __nv_bfloat16* Xl = Xh + 64 * 136;
    int t = threadIdx.x;

    // ---- copy W hi+lo (69632 B = 4352 uint4) ----
    {
        const uint4* src = (const uint4*)wsp;
        uint4* dst = (uint4*)smb;
#pragma unroll
        for (int i = 0; i < 17; i++) {
            int idx = t + i * 256;
            dst[idx] = src[idx];
        }
    }

    // ---- stage X quarter (64 px) hi/lo ----
    int py0 = (n >> 4) * 16, px0 = (n & 15) * 16;
    const float* xb = xin + (size_t)b * CH * HW;
    {
        int px = t & 63;
        int p = q * 64 + px;
        int pix = (py0 + (p >> 4)) * 256 + px0 + (p & 15);
        int cp0 = t >> 6;   // 0..3
#pragma unroll
        for (int j = 0; j < 16; j++) {
            int cp = cp0 + j * 4;
            float v0 = xb[(size_t)(2 * cp) * HW + pix];
            float v1 = xb[(size_t)(2 * cp + 1) * HW + pix];
            __nv_bfloat16 h0 = __float2bfloat16_rn(v0);
            __nv_bfloat16 h1 = __float2bfloat16_rn(v1);
            __nv_bfloat16 l0 = __float2bfloat16_rn(v0 - __bfloat162float(h0));
            __nv_bfloat16 l1 = __float2bfloat16_rn(v1 - __bfloat162float(h1));
            ((__nv_bfloat162*)(Xh + px * 136))[cp] = __nv_bfloat162(h0, h1);
            ((__nv_bfloat162*)(Xl + px * 136))[cp] = __nv_bfloat162(l0, l1);
        }
    }
    __syncthreads();

    // ---- GEMM: 8 warps = 4(oc32) x 2(px32) ----
    int w = t >> 5, lane = t & 31;
    int oc0 = (w & 3) * 32;
    int npx = (w >> 2) * 32;
    int gid = lane >> 2, tig = lane & 3;
    int mm = lane >> 3, r8 = lane & 7;
    uint32_t aoff = (uint32_t)((oc0 + (mm & 1) * 8 + r8) * 272 + (mm >> 1) * 16);
    uint32_t aHi = smaddr(Wh) + aoff;
    uint32_t aLo = smaddr(Wl) + aoff;
    uint32_t boff = (uint32_t)((npx + (mm >> 1) * 8 + r8) * 272 + (mm & 1) * 16);
    uint32_t bHi = smaddr(Xh) + boff;
    uint32_t bLo = smaddr(Xl) + boff;

    float acc[8][4];
#pragma unroll
    for (int i = 0; i < 8; i++)
#pragma unroll
        for (int j = 0; j < 4; j++) acc[i][j] = 0.f;

#pragma unroll 1
    for (int ks = 0; ks < 8; ks++) {
        uint32_t ko = ks * 32;
        uint32_t Ah[2][4], Al[2][4], Bh[2][4], Bl[2][4];
        LDSM_X4(Ah[0], aHi + ko);
        LDSM_X4(Ah[1], aHi + 16 * 272 + ko);
        LDSM_X4(Al[0], aLo + ko);
        LDSM_X4(Al[1], aLo + 16 * 272 + ko);
        LDSM_X4(Bh[0], bHi + ko);
        LDSM_X4(Bh[1], bHi + 16 * 272 + ko);
        LDSM_X4(Bl[0], bLo + ko);
        LDSM_X4(Bl[1], bLo + 16 * 272 + ko);
#pragma unroll
        for (int mt = 0; mt < 2; mt++)
#pragma unroll
            for (int nt = 0; nt < 4; nt++) {
                const uint32_t* bh = &Bh[nt >> 1][(nt & 1) * 2];
                const uint32_t* bl = &Bl[nt >> 1][(nt & 1) * 2];
                MMA_BF16(acc[mt * 4 + nt], Ah[mt], bh);
                MMA_BF16(acc[mt * 4 + nt], Ah[mt], bl);
                MMA_BF16(acc[mt * 4 + nt], Al[mt], bh);
            }
    }

    // ---- epilogue ----
    float* yb = yout + (size_t)b * CH * HW;
#pragma unroll
    for (int mt = 0; mt < 2; mt++) {
        int ocA = oc0 + mt * 16 + gid;
        int ocB = ocA + 8;
        float bvA = __ldg(&bias[ocA]);
        float bvB = __ldg(&bias[ocB]);
#pragma unroll
        for (int nt = 0; nt < 4; nt++) {
            int col = npx + nt * 8 + tig * 2;
            int p = q * 64 + col;
            int pix = (py0 + (p >> 4)) * 256 + px0 + (p & 15);
            float2 v0 = make_float2(acc[mt * 4 + nt][0] + bvA, acc[mt * 4 + nt][1] + bvA);
            float2 v1 = make_float2(acc[mt * 4 + nt][2] + bvB, acc[mt * 4 + nt][3] + bvB);
            *(float2*)(yb + (size_t)ocA * HW + pix) = v0;
            *(float2*)(yb + (size_t)ocB * HW + pix) = v1;
        }
    }
}

// ---------------- fused flow-warp + q/k projections, FULL window (512 thr) ----------------
#define CV_SMEM_FULL ((2 * 128 * 136 + 2 * 256 * 136) * 2)
__global__ void __launch_bounds__(512, 1)
convqk_mma(const float* __restrict__ xin,
           const __nv_bfloat16* __restrict__ wq, const __nv_bfloat16* __restrict__ wk,
           const float* __restrict__ qbias, const float* __restrict__ kbias) {
    int n = blockIdx.x, b = blockIdx.y;
    if (g_MASK[b * 256 + n] == 0.f) return;
    extern __shared__ __nv_bfloat16 smb[];
    __nv_bfloat16* Wh = smb;
    __nv_bfloat16* Wl = Wh + 128 * 136;
    __nv_bfloat16* Xh = Wl + 128 * 136;
    __nv_bfloat16* Xl = Xh + 256 * 136;
    int t = threadIdx.x;

    {
        const uint4* src = (const uint4*)wq;
        uint4* dst = (uint4*)smb;
#pragma unroll
        for (int i = 0; i < 9; i++) {
            int idx = t + i * 512;
            if (idx < 4352) dst[idx] = src[idx];
        }
    }

    int py0 = (n >> 4) * 16, px0 = (n & 15) * 16;
    {
        int px = t & 255;
        int gy = py0 + (px >> 4), gx = px0 + (px & 15);
        int pp = gy * 256 + gx;
        const float* OFb = g_OFF + (size_t)b * 2 * HW;
        float fx = OFb[pp];
        float fy = OFb[HW + pp];
        float sx = fminf(fmaxf((float)gx + fx, 0.f), 255.f);
        float sy = fminf(fmaxf((float)gy + fy, 0.f), 255.f);
        float x0f = floorf(sx), y0f = floorf(sy);
        float x1f = fminf(x0f + 1.f, 255.f), y1f = fminf(y0f + 1.f, 255.f);
        float wx = sx - x0f, wy = sy - y0f;
        int x0 = (int)x0f, x1 = (int)x1f, y0 = (int)y0f, y1 = (int)y1f;
        int iA = y0 * 256 + x0, iB = y0 * 256 + x1, iC = y1 * 256 + x0, iD = y1 * 256 + x1;
        float w00 = (1.f - wx) * (1.f - wy), w01 = wx * (1.f - wy);
        float w10 = (1.f - wx) * wy, w11 = wx * wy;
        const float* xb = xin + (size_t)b * CH * HW;
        int cp0 = t >> 8;
#pragma unroll 4
        for (int j = 0; j < 32; j++) {
            int cp = cp0 + j * 2;
            const float* xc0 = xb + (size_t)(2 * cp) * HW;
            const float* xc1 = xc0 + HW;
            float v0 = __ldg(&xc0[iA]) * w00 + __ldg(&xc0[iB]) * w01 +
                       __ldg(&xc0[iC]) * w10 + __ldg(&xc0[iD]) * w11;
            float v1 = __ldg(&xc1[iA]) * w00 + __ldg(&xc1[iB]) * w01 +
                       __ldg(&xc1[iC]) * w10 + __ldg(&xc1[iD]) * w11;
            __nv_bfloat16 h0 = __float2bfloat16_rn(v0);
            __nv_bfloat16 h1 = __float2bfloat16_rn(v1);
            __nv_bfloat16 l0 = __float2bfloat16_rn(v0 - __bfloat162float(h0));
            __nv_bfloat16 l1 = __float2bfloat16_rn(v1 - __bfloat162float(h1));
            ((__nv_bfloat162*)(Xh + px * 136))[cp] = __nv_bfloat162(h0, h1);
            ((__nv_bfloat162*)(Xl + px * 136))[cp] = __nv_bfloat162(l0, l1);
        }
    }
    __syncthreads();

    int wfull = t >> 5, lane = t & 31;
    int half = wfull >> 3;
    int w = wfull & 7;
    const __nv_bfloat16* XhH = Xh + half * 128 * 136;
    const __nv_bfloat16* XlH = Xl + half * 128 * 136;

    gemm_body_128(Wh, Wl, XhH, XlH, qbias, g_Qb + (size_t)b * CH * HW, py0, px0, half, w, lane);
    __syncthreads();
    {
        const uint4* src = (const uint4*)wk;
        uint4* dst = (uint4*)smb;
#pragma unroll
        for (int i = 0; i < 9; i++) {
            int idx = t + i * 512;
            if (idx < 4352) dst[idx] = src[idx];
        }
    }
    __syncthreads();
    gemm_body_128(Wh, Wl, XhH, XlH, kbias, g_Kb + (size_t)b * CH * HW, py0, px0, half, w, lane);
}

// ---------------- predictor: tensor-core phase-1, per-pixel phase-2 ----------------
#define PRED2_SMEM (69632*2 + 8704*2 + 33408 + 2048 + 128 + 1024 + 128)
__global__ void __launch_bounds__(512, 1)
predictor_mma(const float* __restrict__ cond_g,
              const float* __restrict__ rin_w, const float* __restrict__ rin_b,
              const float* __restrict__ r1w, const float* __restrict__ r1b,
              const float* __restrict__ r2w, const float* __restrict__ r2b) {
    int n = blockIdx.x, b = blockIdx.y;
    extern __shared__ char smraw[];
    __nv_bfloat16* Xh = (__nv_bfloat16*)smraw;
    __nv_bfloat16* Xl = Xh + 256 * 136;
    __nv_bfloat16* Wh = Xl + 256 * 136;
    __nv_bfloat16* Wl = Wh + 32 * 136;
    float* fS = (float*)(Wl + 32 * 136);   // 32*261
    float* wr1 = fS + 32 * 261;            // 16*32
    float* wr2 = wr1 + 16 * 32;            // 32
    float* cgS = wr2 + 32;                 // 256
    float* fsum_s = cgS + 256;             // 32
    int t = threadIdx.x;

    {
        const uint4* src = (const uint4*)g_WRIN;
        uint4* dst = (uint4*)Wh;
#pragma unroll
        for (int i = 0; i < 3; i++) {
            int idx = t + i * 512;
            if (idx < 1088) dst[idx] = src[idx];
        }
    }
    for (int i = t; i < 16 * 32; i += 512) wr1[i] = r1w[i];
    if (t < 32) { wr2[t] = r2w[t]; fsum_s[t] = 0.f; }

    int py0 = (n >> 4) * 16, px0 = (n & 15) * 16;
    if (t < 256) {
        int pix = (py0 + (t >> 4)) * 256 + px0 + (t & 15);
        cgS[t] = __ldg(&cond_g[(size_t)b * HW + pix]);
    }
    const float* xb = g_V + (size_t)b * CH * HW;
    {
        int px = t & 255;
        int pix = (py0 + (px >> 4)) * 256 + px0 + (px & 15);
        int cp0 = t >> 8;
#pragma unroll
        for (int j = 0; j < 32; j++) {
            int cp = cp0 + j * 2;
            float v0 = xb[(size_t)(2 * cp) * HW + pix];
            float v1 = xb[(size_t)(2 * cp + 1) * HW + pix];
            __nv_bfloat16 h0 = __float2bfloat16_rn(v0);
            __nv_bfloat16 h1 = __float2bfloat16_rn(v1);
            __nv_bfloat16 l0 = __float2bfloat16_rn(v0 - __bfloat162float(h0));
            __nv_bfloat16 l1 = __float2bfloat16_rn(v1 - __bfloat162float(h1));
            ((__nv_bfloat162*)(Xh + px * 136))[cp] = __nv_bfloat162(h0, h1);
            ((__nv_bfloat162*)(Xl + px * 136))[cp] = __nv_bfloat162(l0, l1);
        }
    }
    __syncthreads();

    // GEMM: 16 warps = 2(m16) x 8(n32)
    int w = t >> 5, lane = t & 31;
    int gid = lane >> 2, tig = lane & 3;
    int mm = lane >> 3, r8 = lane & 7;
    int mrow = (w & 1) * 16;
    int ncol = (w >> 1) * 32;
    uint32_t aoff = (uint32_t)((mrow + (mm & 1) * 8 + r8) * 272 + (mm >> 1) * 16);
    uint32_t aHi = smaddr(Wh) + aoff;
    uint32_t aLo = smaddr(Wl) + aoff;
    uint32_t boff = (uint32_t)((ncol + (mm >> 1) * 8 + r8) * 272 + (mm & 1) * 16);
    uint32_t bHi = smaddr(Xh) + boff;
    uint32_t bLo = smaddr(Xl) + boff;

    float acc[4][4];
#pragma unroll
    for (int i = 0; i < 4; i++)
#pragma unroll
        for (int j = 0; j < 4; j++) acc[i][j] = 0.f;
#pragma unroll 1
    for (int ks = 0; ks < 8; ks++) {
        uint32_t ko = ks * 32;
        uint32_t Ah[4], Al[4], Bh[2][4], Bl[2][4];
        LDSM_X4(Ah, aHi + ko);
        LDSM_X4(Al, aLo + ko);
        LDSM_X4(Bh[0], bHi + ko);
        LDSM_X4(Bl[0], bLo + ko);
        LDSM_X4(Bh[1], bHi + 16 * 272 + ko);
        LDSM_X4(Bl[1], bLo + 16 * 272 + ko);
#pragma unroll
        for (int nt = 0; nt < 4; nt++) {
            const uint32_t* bh = &Bh[nt >> 1][(nt & 1) * 2];
            const uint32_t* bl = &Bl[nt >> 1][(nt & 1) * 2];
            MMA_BF16(acc[nt], Ah, bh);
            MMA_BF16(acc[nt], Ah, bl);
            MMA_BF16(acc[nt], Al, bh);
        }
    }

    {
        int ocA = mrow + gid, ocB = ocA + 8;
        float bA = __ldg(&rin_b[ocA]), bB = __ldg(&rin_b[ocB]);
        float wA128 = __ldg(&rin_w[ocA * 131 + 128]);
        float wA129 = __ldg(&rin_w[ocA * 131 + 129]);
        float wA130 = __ldg(&rin_w[ocA * 131 + 130]);
        float wB128 = __ldg(&rin_w[ocB * 131 + 128]);
        float wB129 = __ldg(&rin_w[ocB * 131 + 129]);
        float wB130 = __ldg(&rin_w[ocB * 131 + 130]);
        float* Fb = g_F + (size_t)b * 32 * HW;
        float sA = 0.f, sB = 0.f;
#pragma unroll
        for (int nt = 0; nt < 4; nt++) {
            int col = ncol + nt * 8 + tig * 2;
#pragma unroll
            for (int d = 0; d < 2; d++) {
                int px = col + d;
                float cg = cgS[px];
                float ly = -1.f + (float)(px >> 4) * (2.f / 15.f);
                float lx = -1.f + (float)(px & 15) * (2.f / 15.f);
                float vA = leakyf(acc[nt][d] + bA + wA128 * cg + wA129 * ly + wA130 * lx);
                float vB = leakyf(acc[nt][2 + d] + bB + wB128 * cg + wB129 * ly + wB130 * lx);
                fS[ocA * 261 + px] = vA;
                fS[ocB * 261 + px] = vB;
                sA += vA; sB += vB;
                int pix = (py0 + (px >> 4)) * 256 + px0 + (px & 15);
                Fb[(size_t)ocA * HW + pix] = vA;
                Fb[(size_t)ocB * HW + pix] = vB;
            }
        }
        atomicAdd(&fsum_s[ocA], sA);
        atomicAdd(&fsum_s[ocB], sB);
    }
    __syncthreads();

    if (t < 256) {
        int px = t;
        float fv[32];
        float fm = 0.f;
#pragma unroll
        for (int o = 0; o < 32; o++) {
            fv[o] = fS[o * 261 + px];
            fm += fv[o];
        }
        int pix = (py0 + (px >> 4)) * 256 + px0 + (px & 15);
        g_FMC[(size_t)b * HW + pix] = fm * (1.f / 32.f);

        float h[16];
#pragma unroll
        for (int o2 = 0; o2 < 16; o2++) {
            float s = __ldg(&r1b[o2]);
#pragma unroll
            for (int o = 0; o < 32; o++) s = fmaf(wr1[o2 * 32 + o], fv[o], s);
            h[o2] = leakyf(s);
        }
        float ox = __ldg(&r2b[0]), oy = __ldg(&r2b[1]);
#pragma unroll
        for (int o2 = 0; o2 < 16; o2++) {
            ox = fmaf(wr2[o2], h[o2], ox);
            oy = fmaf(wr2[16 + o2], h[o2], oy);
        }
        float* OFb = g_OFF + (size_t)b * 2 * HW;
        OFb[pix] = ox;
        OFb[HW + pix] = oy;
    }
    __syncthreads();
    if (t < 32) atomicAdd(&g_FSUM[b * 32 + t], fsum_s[t]);
}

// ---------------- channel attention ca ----------------
__global__ void ca_kernel(const float* __restrict__ rca_w, const float* __restrict__ rca_b) {
    int c = threadIdx.x;
    int b = blockIdx.x;
    float s = __ldg(&rca_b[c]);
#pragma unroll
    for (int ci = 0; ci < 32; ci++)
        s = fmaf(__ldg(&rca_w[c * 32 + ci]), g_FSUM[b * 32 + ci] * (1.f / 65536.f), s);
    g_CA[b * CH + c] = 1.f / (1.f + expf(-s));
}

// ---------------- spatial attention sa: 2D-tiled ----------------
__global__ void __launch_bounds__(256) sa_kernel(const float* __restrict__ rsa_w,
                                                 const float* __restrict__ rsa_b) {
    __shared__ float ws[288];
    __shared__ float tile[10][36];
    int t = threadIdx.x;
    for (int i = t; i < 288; i += 256) ws[i] = rsa_w[i];
    int b = blockIdx.z;
    int tx0 = blockIdx.x * 32, ty0 = blockIdx.y * 8;
    int lx = t & 31, lyy = t >> 5;
    float acc = __ldg(&rsa_b[0]);
    const float* Fb = g_F + (size_t)b * 32 * HW;
#pragma unroll 1
    for (int ci = 0; ci < 32; ci++) {
        __syncthreads();
        for (int i = t; i < 340; i += 256) {
            int lyl = i / 34, lxl = i % 34;
            int gy = ty0 - 1 + lyl, gx = tx0 - 1 + lxl;
            float v = 0.f;
            if ((unsigned)gy < 256u && (unsigned)gx < 256u)
                v = __ldg(&Fb[(size_t)ci * HW + gy * 256 + gx]);
            tile[lyl][lxl] = v;
        }
        __syncthreads();
        const float* wc = ws + ci * 9;
#pragma unroll
        for (int ky = 0; ky < 3; ky++)
#pragma unroll
            for (int kx = 0; kx < 3; kx++)
                acc = fmaf(wc[ky * 3 + kx], tile[lyy + ky][lx + kx], acc);
    }
    g_SA[(size_t)b * HW + (ty0 + lyy) * 256 + tx0 + lx] = 1.f / (1.f + expf(-acc));
}

// ---------------- window MLP + gumbel hard mask ----------------
__global__ void mask_kernel(const float* __restrict__ gu,
                            const float* __restrict__ rm1_w, const float* __restrict__ rm1_b,
                            const float* __restrict__ rm2_w, const float* __restrict__ rm2_b) {
    __shared__ float m[256];
    __shared__ float h1s[16];
    int n = blockIdx.x, b = blockIdx.y;
    int t = threadIdx.x;
    int dh = t >> 4, dw = t & 15;
    int pix = ((n >> 4) * 16 + dh) * 256 + (n & 15) * 16 + dw;
    m[t] = g_FMC[b * HW + pix];
    __syncthreads();
    if (t < 16) {
        float s = __ldg(&rm1_b[t]);
        for (int e = 0; e < 256; e++) s = fmaf(__ldg(&rm1_w[t * 256 + e]), m[e], s);
        h1s[t] = leakyf(s);
    }
    __syncthreads();
    if (t == 0) {
        float z0 = __ldg(&rm2_b[0]), z1 = __ldg(&rm2_b[1]);
#pragma unroll
        for (int o = 0; o < 16; o++) {
            z0 = fmaf(__ldg(&rm2_w[o]), h1s[o], z0);
            z1 = fmaf(__ldg(&rm2_w[16 + o]), h1s[o], z1);
        }
        float mx = fmaxf(z0, z1);
        float e0 = expf(z0 - mx), e1 = expf(z1 - mx);
        float inv = 1.f / (e0 + e1);
        float p0 = e0 * inv, p1 = e1 * inv;
        float u0 = __ldg(&gu[(b * 256 + n) * 2 + 0]);
        float u1 = __ldg(&gu[(b * 256 + n) * 2 + 1]);
        float g0 = -logf(-logf(u0 + 1e-10f) + 1e-10f);
        float g1 = -logf(-logf(u1 + 1e-10f) + 1e-10f);
        g_MASK[b * 256 + n] = (p0 + g0 >= p1 + g1) ? 1.f : 0.f;
    }
}

// ---------------- v*sa copy for unmasked windows (no smem, high occupancy) ----------------
__global__ void __launch_bounds__(256) vsa_kernel() {
    int n = blockIdx.x, b = blockIdx.y;
    if (g_MASK[b * 256 + n] != 0.f) return;
    int py0 = (n >> 4) * 16, px0 = (n & 15) * 16;
    int cbase = b * CH * HW;
    const float* sab = g_SA + (size_t)b * HW;
    int t = threadIdx.x;
#pragma unroll 4
    for (int i = t; i < 8192; i += 256) {
        int ch = i >> 6, r4 = i & 63;
        int wrow = r4 >> 2, px4 = (r4 & 3) * 4;
        int pix = (py0 + wrow) * 256 + px0 + px4;
        float4 v = *(const float4*)(g_V + cbase + ch * HW + pix);
        float4 s = *(const float4*)(sab + pix);
        v.x *= s.x; v.y *= s.y; v.z *= s.z; v.w *= s.w;
        *(float4*)(g_OUT + cbase + ch * HW + pix) = v;
    }
}

// ---------------- window attention, 512 threads (16 warps), ldmatrix fragments ----------------
#define SMEM_ATTN3 ((64*257 + 512 + 64 + 64) * 4 + 90112)
__global__ void __launch_bounds__(512, 1) attn_mma_kernel() {
    int n = blockIdx.x, b = blockIdx.y;
    int t = threadIdx.x;
    int py0 = (n >> 4) * 16, px0 = (n & 15) * 16;
    int cbase = b * CH * HW;
    if (g_MASK[b * 256 + n] == 0.f) return;   // handled by vsa_kernel
    extern __shared__ char smraw[];
    float* S = (float*)smraw;
    float* red = S + 64 * 257;
    float* rmax = red + 512;
    float* rsum = rmax + 64;
    __nv_bfloat16* Qh = (__nv_bfloat16*)(rsum + 64);
    __nv_bfloat16* Ql = Qh + 64 * 136;
    __nv_bfloat16* KVh = Ql + 64 * 136;
    __nv_bfloat16* KVl = KVh + 9216;
    __nv_bfloat16* Pth = KVl + 9216;
    __nv_bfloat16* Ptl = Pth + 64 * 72;

    int w = t >> 5, lane = t & 31;
    int gid = lane >> 2;
    int tig = lane & 3;
    int mm = lane >> 3, r8 = lane & 7;

    int mrowS = (w & 3) * 16, ncolS = (w >> 2) * 16;
    uint32_t aoffS = (uint32_t)((mrowS + (mm & 1) * 8 + r8) * 272 + (mm >> 1) * 16);
    uint32_t aHiS = smaddr(Qh) + aoffS;
    uint32_t aLoS = smaddr(Ql) + aoffS;
    uint32_t boffS = (uint32_t)((ncolS + (mm >> 1) * 8 + r8) * 272 + (mm & 1) * 16);
    uint32_t bHiS = smaddr(KVh) + boffS;
    uint32_t bLoS = smaddr(KVl) + boffS;

    int mrowO = (w & 3) * 16, ncolO = (w >> 2) * 32;
    uint32_t aoffP = (uint32_t)((mrowO + (mm & 1) * 8 + r8) * 144 + (mm >> 1) * 16);
    uint32_t aHiP = smaddr(Pth) + aoffP;
    uint32_t aLoP = smaddr(Ptl) + aoffP;
    uint32_t boffP = (uint32_t)((ncolO + (mm >> 1) * 8 + r8) * 144 + (mm & 1) * 16);
    uint32_t bHiP = smaddr(KVh) + boffP;
    uint32_t bLoP = smaddr(KVl) + boffP;

#pragma unroll 1
    for (int rc = 0; rc < 4; rc++) {
        int r0 = rc * 64;
        __syncthreads();
#pragma unroll
        for (int j = 0; j < 8; j++) {
            int i = t + j * 512;
            int px = i & 63, cp = i >> 6;
            int p = r0 + px;
            int pix = (py0 + (p >> 4)) * 256 + px0 + (p & 15);
            float v0 = g_Qb[cbase + (2 * cp) * HW + pix];
            float v1 = g_Qb[cbase + (2 * cp + 1) * HW + pix];
            __nv_bfloat16 h0 = __float2bfloat16_rn(v0);
            __nv_bfloat16 h1 = __float2bfloat16_rn(v1);
            __nv_bfloat16 l0 = __float2bfloat16_rn(v0 - __bfloat162float(h0));
            __nv_bfloat16 l1 = __float2bfloat16_rn(v1 - __bfloat162float(h1));
            ((__nv_bfloat162*)(Qh + px * 136))[cp] = __nv_bfloat162(h0, h1);
            ((__nv_bfloat162*)(Ql + px * 136))[cp] = __nv_bfloat162(l0, l1);
        }

#pragma unroll 1
        for (int kvt = 0; kvt < 4; kvt++) {
            __syncthreads();
#pragma unroll
            for (int j = 0; j < 8; j++) {
                int i = t + j * 512;
                int px = i & 63, cp = i >> 6;
                int p = kvt * 64 + px;
                int pix = (py0 + (p >> 4)) * 256 + px0 + (p & 15);
                float v0 = g_Kb[cbase + (2 * cp) * HW + pix];
                float v1 = g_Kb[cbase + (2 * cp + 1) * HW + pix];
                __nv_bfloat16 h0 = __float2bfloat16_rn(v0);
                __nv_bfloat16 h1 = __float2bfloat16_rn(v1);
                __nv_bfloat16 l0 = __float2bfloat16_rn(v0 - __bfloat162float(h0));
                __nv_bfloat16 l1 = __float2bfloat16_rn(v1 - __bfloat162float(h1));
                ((__nv_bfloat162*)(KVh + px * 136))[cp] = __nv_bfloat162(h0, h1);
                ((__nv_bfloat162*)(KVl + px * 136))[cp] = __nv_bfloat162(l0, l1);
            }
            __syncthreads();
            float acc[2][4];
#pragma unroll
            for (int i = 0; i < 2; i++)
#pragma unroll
                for (int j2 = 0; j2 < 4; j2++) acc[i][j2] = 0.f;
#pragma unroll
            for (int ks = 0; ks < 8; ks++) {
                uint32_t ko = ks * 32;
                uint32_t Ahf[4], Alf[4], Bhf[4], Blf[4];
                LDSM_X4(Ahf, aHiS + ko);
                LDSM_X4(Alf, aLoS + ko);
                LDSM_X4(Bhf, bHiS + ko);
                LDSM_X4(Blf, bLoS + ko);
#pragma unroll
                for (int nt = 0; nt < 2; nt++) {
                    const uint32_t* bh = &Bhf[nt * 2];
                    const uint32_t* bl = &Blf[nt * 2];
                    MMA_BF16(acc[nt], Ahf, bh);
                    MMA_BF16(acc[nt], Ahf, bl);
                    MMA_BF16(acc[nt], Alf, bh);
                }
            }
#pragma unroll
            for (int nt = 0; nt < 2; nt++) {
                int col = kvt * 64 + ncolS + nt * 8 + tig * 2;
                S[(mrowS + gid) * 257 + col] = acc[nt][0];
                S[(mrowS + gid) * 257 + col + 1] = acc[nt][1];
                S[(mrowS + gid + 8) * 257 + col] = acc[nt][2];
                S[(mrowS + gid + 8) * 257 + col + 1] = acc[nt][3];
            }
        }
        __syncthreads();

        {
            int r = t & 63, seg = t >> 6;
            float* srow = &S[r * 257 + seg * 32];
            float mx = -1e30f;
#pragma unroll 8
            for (int k = 0; k < 32; k++) mx = fmaxf(mx, srow[k]);
            red[seg * 64 + r] = mx;
            __syncthreads();
            if (t < 64) {
                float m0 = fmaxf(fmaxf(red[t], red[64 + t]), fmaxf(red[128 + t], red[192 + t]));
                float m1 = fmaxf(fmaxf(red[256 + t], red[320 + t]), fmaxf(red[384 + t], red[448 + t]));
                rmax[t] = fmaxf(m0, m1);
            }
            __syncthreads();
            float rm_ = rmax[r];
            float s = 0.f;
#pragma unroll 8
            for (int k = 0; k < 32; k++) {
                float e = __expf(srow[k] - rm_);
                srow[k] = e;
                s += e;
            }
            red[seg * 64 + r] = s;
            __syncthreads();
            if (t < 64)
                rsum[t] = (red[t] + red[64 + t] + red[128 + t] + red[192 + t]) +
                          (red[256 + t] + red[320 + t] + red[384 + t] + red[448 + t]);
            __syncthreads();
        }

        float oacc[4][4];
#pragma unroll
        for (int i = 0; i < 4; i++)
#pragma unroll
            for (int j2 = 0; j2 < 4; j2++) oacc[i][j2] = 0.f;

#pragma unroll 1
        for (int kvt = 0; kvt < 4; kvt++) {
            __syncthreads();
#pragma unroll
            for (int j = 0; j < 8; j++) {
                int i = t + j * 512;
                int col = i & 63, row = i >> 6;
                float v = S[row * 257 + kvt * 64 + col];
                __nv_bfloat16 h = __float2bfloat16_rn(v);
                Pth[row * 72 + col] = h;
                Ptl[row * 72 + col] = __float2bfloat16_rn(v - __bfloat162float(h));
            }
#pragma unroll
            for (int j = 0; j < 16; j++) {
                int i = t + j * 512;
                int px = i & 63, ch = i >> 6;
                int p = kvt * 64 + px;
                int pix = (py0 + (p >> 4)) * 256 + px0 + (p & 15);
                float v = g_V[cbase + ch * HW + pix];
                __nv_bfloat16 h = __float2bfloat16_rn(v);
                KVh[ch * 72 + px] = h;
                KVl[ch * 72 + px] = __float2bfloat16_rn(v - __bfloat162float(h));
            }
            __syncthreads();
#pragma unroll
            for (int ks = 0; ks < 4; ks++) {
                uint32_t ko = ks * 32;
                uint32_t Ahf[4], Alf[4], Bhf[2][4], Blf[2][4];
                LDSM_X4(Ahf, aHiP + ko);
                LDSM_X4(Alf, aLoP + ko);
                LDSM_X4(Bhf[0], bHiP + ko);
                LDSM_X4(Blf[0], bLoP + ko);
                LDSM_X4(Bhf[1], bHiP + 16 * 144 + ko);
                LDSM_X4(Blf[1], bLoP + 16 * 144 + ko);
#pragma unroll
                for (int nt = 0; nt < 4; nt++) {
                    const uint32_t* bh = &Bhf[nt >> 1][(nt & 1) * 2];
                    const uint32_t* bl = &Blf[nt >> 1][(nt & 1) * 2];
                    MMA_BF16(oacc[nt], Ahf, bh);
                    MMA_BF16(oacc[nt], Ahf, bl);
                    MMA_BF16(oacc[nt], Alf, bh);
                }
            }
        }

        {
            int rowA = mrowO + gid, rowB = rowA + 8;
            float invA = 1.f / rsum[rowA];
            float invB = 1.f / rsum[rowB];
            int pA = r0 + rowA, pB = r0 + rowB;
            int pixA = (py0 + (pA >> 4)) * 256 + px0 + (pA & 15);
            int pixB = (py0 + (pB >> 4)) * 256 + px0 + (pB & 15);
#pragma unroll
            for (int nt = 0; nt < 4; nt++) {
                int ch = ncolO + nt * 8 + tig * 2;
                g_OUT[cbase + ch * HW + pixA] = oacc[nt][0] * invA;
                g_OUT[cbase + (ch + 1) * HW + pixA] = oacc[nt][1] * invA;
                g_OUT[cbase + ch * HW + pixB] = oacc[nt][2] * invB;
                g_OUT[cbase + (ch + 1) * HW + pixB] = oacc[nt][3] * invB;
            }
        }
    }
}

// ---------------- fused depthwise 5x5(d1) -> 5x5(d3) + gelu*ca + residual ----------------
__global__ void __launch_bounds__(256) dw5x2_kernel(
    const float* __restrict__ in, const float* __restrict__ w2, const float* __restrict__ b2,
    const float* __restrict__ w3, const float* __restrict__ b3, float* __restrict__ out) {
    __shared__ float sIn[48][81];
    __shared__ float sMid[44][77];
    __shared__ float wA[25], wB[25];
    int c = blockIdx.z & 127, b = blockIdx.z >> 7;
    int t = threadIdx.x;
    if (t < 25) wA[t] = w2[c * 25 + t];
    else if (t < 50) wB[t - 25] = w3[c * 25 + (t - 25)];
    int ox0 = blockIdx.x * 64, oy0 = blockIdx.y * 32;
    const float* ip = in + (size_t)(b * CH + c) * HW;

    for (int i = t; i < 48 * 80; i += 256) {
        int lx = i % 80, ly = i / 80;
        int gx = ox0 - 8 + lx, gy = oy0 - 8 + ly;
        float v = 0.f;
        if ((unsigned)gx < 256u && (unsigned)gy < 256u) v = __ldg(&ip[gy * 256 + gx]);
        sIn[ly][lx] = v;
    }
    __syncthreads();

    float b2v = __ldg(&b2[c]);
    for (int i = t; i < 44 * 76; i += 256) {
        int mx = i % 76, my = i / 76;
        int gx = ox0 - 6 + mx, gy = oy0 - 6 + my;
        float acc = 0.f;
        if ((unsigned)gx < 256u && (unsigned)gy < 256u) {
            acc = b2v;
#pragma unroll
            for (int ky = 0; ky < 5; ky++)
#pragma unroll
                for (int kx = 0; kx < 5; kx++)
                    acc = fmaf(wA[ky * 5 + kx], sIn[my + ky][mx + kx], acc);
        }
        sMid[my][mx] = acc;
    }
    __syncthreads();

    float b3v = __ldg(&b3[c]);
    float cav = g_CA[b * CH + c];
    size_t obase = (size_t)(b * CH + c) * HW;
    for (int i = t; i < 32 * 64; i += 256) {
        int x = i % 64, y = i / 64;
        float acc = b3v;
#pragma unroll
        for (int ky = 0; ky < 5; ky++)
#pragma unroll
            for (int kx = 0; kx < 5; kx++)
                acc = fmaf(wB[ky * 5 + kx], sMid[y + 3 * ky][x + 3 * kx], acc);
        float g = 0.5f * acc * (1.f + erff(acc * 0.7071067811865475f));
        size_t oidx = obase + (size_t)(oy0 + y) * 256 + ox0 + x;
        out[oidx] = g * cav + g_OUT[oidx];
    }
}

// ---------------- launch ----------------
extern "C" void kernel_launch(void* const* d_in, const int* in_sizes, int n_in,
                              void* d_out, int out_size) {
    const float* x      = (const float*)d_in[0];
    const float* cond_g = (const float*)d_in[1];
    const float* gu     = (const float*)d_in[2];
    const float* pv_w   = (const float*)d_in[3];
    const float* pv_b   = (const float*)d_in[4];
    const float* pq_w   = (const float*)d_in[5];
    const float* pq_b   = (const float*)d_in[6];
    const float* pk_w   = (const float*)d_in[7];
    const float* pk_b   = (const float*)d_in[8];
    const float* cs1_w  = (const float*)d_in[9];
    const float* cs1_b  = (const float*)d_in[10];
    const float* cs2_w  = (const float*)d_in[11];
    const float* cs2_b  = (const float*)d_in[12];
    const float* cs3_w  = (const float*)d_in[13];
    const float* cs3_b  = (const float*)d_in[14];
    const float* po_w   = (const float*)d_in[15];
    const float* po_b   = (const float*)d_in[16];
    const float* rin_w  = (const float*)d_in[17];
    const float* rin_b  = (const float*)d_in[18];
    const float* r1w    = (const float*)d_in[19];
    const float* r1b    = (const float*)d_in[20];
    const float* r2w    = (const float*)d_in[21];
    const float* r2b    = (const float*)d_in[22];
    const float* rm1_w  = (const float*)d_in[23];
    const float* rm1_b  = (const float*)d_in[24];
    const float* rm2_w  = (const float*)d_in[25];
    const float* rm2_b  = (const float*)d_in[26];
    const float* rca_w  = (const float*)d_in[27];
    const float* rca_b  = (const float*)d_in[28];
    const float* rsa_w  = (const float*)d_in[29];
    const float* rsa_b  = (const float*)d_in[30];

    float *pV, *pOUT, *pT1, *pT2;
    __nv_bfloat16* pWT;
    cudaGetSymbolAddress((void**)&pV, g_V);
    cudaGetSymbolAddress((void**)&pOUT, g_OUT);
    cudaGetSymbolAddress((void**)&pT1, g_T1);
    cudaGetSymbolAddress((void**)&pT2, g_T2);
    cudaGetSymbolAddress((void**)&pWT, g_WT);

    cudaFuncSetAttribute(attn_mma_kernel, cudaFuncAttributeMaxDynamicSharedMemorySize, SMEM_ATTN3);
    cudaFuncSetAttribute(conv1x1_mma, cudaFuncAttributeMaxDynamicSharedMemorySize, CV_SMEM_Q);
    cudaFuncSetAttribute(convqk_mma, cudaFuncAttributeMaxDynamicSharedMemorySize, CV_SMEM_FULL);
    cudaFuncSetAttribute(predictor_mma, cudaFuncAttributeMaxDynamicSharedMemorySize, PRED2_SMEM);

    const int WSET = 2 * 128 * 136;

    prep_all_kernel<<<dim3(64, 5), 256>>>(pv_w, pq_w, pk_w, cs1_w, po_w);
    prep_rin_kernel<<<16, 256>>>(rin_w);
    zero_fsum_kernel<<<1, 128>>>();
    conv1x1_mma<<<dim3(1024, BB), 256, CV_SMEM_Q>>>(x, pWT + 0 * WSET, pv_b, pV, 0);
    predictor_mma<<<dim3(256, BB), 512, PRED2_SMEM>>>(cond_g, rin_w, rin_b, r1w, r1b, r2w, r2b);
    ca_kernel<<<BB, 128>>>(rca_w, rca_b);
    sa_kernel<<<dim3(8, 32, BB), 256>>>(rsa_w, rsa_b);
    mask_kernel<<<dim3(256, BB), 256>>>(gu, rm1_w, rm1_b, rm2_w, rm2_b);
    convqk_mma<<<dim3(256, BB), 512, CV_SMEM_FULL>>>(x, pWT + 1 * WSET, pWT + 2 * WSET, pq_b, pk_b);
    vsa_kernel<<<dim3(256, BB), 256>>>();
    attn_mma_kernel<<<dim3(256, BB), 512, SMEM_ATTN3>>>();
    conv1x1_mma<<<dim3(1024, BB), 256, CV_SMEM_Q>>>(pOUT, pWT + 3 * WSET, cs1_b, pT1, 0);
    dw5x2_kernel<<<dim3(4, 8, BB * CH), 256>>>(pT1, cs2_w, cs2_b, cs3_w, cs3_b, pT2);
    conv1x1_mma<<<dim3(1024, BB), 256, CV_SMEM_Q>>>(pT2, pWT + 4 * WSET, po_b, (float*)d_out, 0);
}